// round 8
// baseline (speedup 1.0000x reference)
#include <cuda_runtime.h>
#include <cstdint>
#include <cstddef>

// CTC batch cost (keras ctc_batch_cost), prob-domain forward, exact biased
// power-of-2 rescaling. One warp handles TWO batch elements (interleaved
// independent recurrences). Ring: 6 slots x 32KB (16 rows x 1KB per element).
// Grid 128 CTAs -> <=1 CTA/SM. B=256,T=512,C=256(blank=255),U=64,S=129.
static constexpr int Bn = 256, Tn = 512, Cn = 256, Un = 64;
static constexpr int BLANK = Cn - 1;
static constexpr float EPSF = 1e-7f;
static constexpr float Kc = 256.f;      // exact power of 2
static constexpr float EK = 256.f * EPSF;
static constexpr int   BIAS = 48;       // pins working level ~2^48: no FTZ
static constexpr int   NSLOT = 6;
static constexpr int   SLOT_FLOATS = 8192;           // 32KB: [A 16 rows][B 16 rows]
static constexpr int   SMEM_TOTAL = NSLOT * 32768;   // 192KB

__device__ __forceinline__ void mwait(uint32_t mbar, uint32_t parity) {
    asm volatile(
        "{\n\t.reg .pred P;\n"
        "WL_%=:\n\t"
        "mbarrier.try_wait.parity.acquire.cta.shared::cta.b64 P, [%0], %1, 0x989680;\n\t"
        "@P bra WD_%=;\n\t"
        "bra WL_%=;\n"
        "WD_%=:\n\t}"
        :: "r"(mbar), "r"(parity) : "memory");
}

// lane 0 (predicated): expect 32KB, two 16KB bulk copies into one slot
__device__ __forceinline__ void bulk_fill2(uint32_t mbar, uint32_t sdst,
                                           const float* gA, const float* gB,
                                           int lane) {
    asm volatile(
        "{\n\t.reg .pred P;\n\t"
        "setp.eq.s32 P, %4, 0;\n\t"
        "@P mbarrier.arrive.expect_tx.shared.b64 _, [%0], 32768;\n\t"
        "@P cp.async.bulk.shared::cta.global.mbarrier::complete_tx::bytes [%1], [%2], 16384, [%0];\n\t"
        "@P cp.async.bulk.shared::cta.global.mbarrier::complete_tx::bytes [%3], [%5], 16384, [%0];\n\t"
        "}"
        :: "r"(mbar), "r"(sdst), "l"(gA), "r"(sdst + 16384u), "r"(lane), "l"(gB)
        : "memory");
}

// Lane L owns states 4L..4L+3; a4 = state 128 on lane 31 only (0 elsewhere).
__device__ __forceinline__ void dp_step(float& a0, float& a1, float& a2,
                                        float& a3, float& a4,
                                        float vB, float v0, float v1,
                                        float sk1, float sk3, int lane) {
    float pa3 = __shfl_up_sync(0xffffffffu, a3, 1);
    if (lane == 0) pa3 = 0.f;
    float na0 = (a0 + pa3) * vB;
    float na1 = fmaf(sk1, pa3, a0 + a1) * v0;
    float na2 = (a1 + a2) * vB;
    float na3 = fmaf(sk3, a1, a2 + a3) * v1;
    float na4 = (lane == 31) ? (a3 + a4) * vB : 0.f;
    a0 = na0; a1 = na1; a2 = na2; a3 = na3; a4 = na4;
}

#define LOADV2(OFF)                                                          \
    { _Pragma("unroll") for (int i_ = 0; i_ < 4; i_++) {                     \
        vBa[i_] = fmaf(pBl[(OFF) + i_ * Cn], Kc, EK);                        \
        v0a[i_] = fmaf(p0a[(OFF) + i_ * Cn], Kc, EK);                        \
        v1a[i_] = fmaf(p1a[(OFF) + i_ * Cn], Kc, EK);                        \
        vBb[i_] = fmaf(pBl[(OFF) + 4096 + i_ * Cn], Kc, EK);                 \
        v0b[i_] = fmaf(p0b[(OFF) + 4096 + i_ * Cn], Kc, EK);                 \
        v1b[i_] = fmaf(p1b[(OFF) + 4096 + i_ * Cn], Kc, EK); } }

#define APPLY1(bf_, E_, x0, x1, x2, x3, x4)                                  \
    { uint32_t bb_ = __float_as_uint(bf_);                                   \
      int sh_ = (int)(bb_ >> 23) - 127 - BIAS;                               \
      if (sh_ < -120) sh_ = -120;                                            \
      E_ += sh_;                                                             \
      float r_ = __uint_as_float((uint32_t)(127 - sh_) << 23);               \
      x0 *= r_; x1 *= r_; x2 *= r_; x3 *= r_; x4 *= r_; }

#define DPSA(i_) dp_step(aA0,aA1,aA2,aA3,aA4, vBa[i_],v0a[i_],v1a[i_], sk1a,sk3a, lane)
#define DPSB(i_) dp_step(aB0,aB1,aB2,aB3,aB4, vBb[i_],v0b[i_],v1b[i_], sk1b,sk3b, lane)

#define GRPA2(OFF)                                                           \
    { float vBa[4],v0a[4],v1a[4],vBb[4],v0b[4],v1b[4]; LOADV2(OFF);          \
      APPLY1(bfA, Ea, aA0, aA1, aA2, aA3, aA4);                              \
      APPLY1(bfB, Eb, aB0, aB1, aB2, aB3, aB4);                              \
      DPSA(0); DPSB(0); DPSA(1); DPSB(1);                                    \
      DPSA(2); DPSB(2); DPSA(3); DPSB(3);                                    \
      lsA = ((aA0 + aA1) + (aA2 + aA3)) + aA4;                               \
      lsA += __shfl_xor_sync(0xffffffffu, lsA, 16);                          \
      lsB = ((aB0 + aB1) + (aB2 + aB3)) + aB4;                               \
      lsB += __shfl_xor_sync(0xffffffffu, lsB, 16); }

#define GRPB2(OFF)                                                           \
    { float vBa[4],v0a[4],v1a[4],vBb[4],v0b[4],v1b[4]; LOADV2(OFF);          \
      DPSA(0); DPSB(0);                                                      \
      lsA += __shfl_xor_sync(0xffffffffu, lsA, 8);                           \
      lsB += __shfl_xor_sync(0xffffffffu, lsB, 8);                           \
      DPSA(1); DPSB(1);                                                      \
      lsA += __shfl_xor_sync(0xffffffffu, lsA, 4);                           \
      lsB += __shfl_xor_sync(0xffffffffu, lsB, 4);                           \
      DPSA(2); DPSB(2);                                                      \
      lsA += __shfl_xor_sync(0xffffffffu, lsA, 2);                           \
      lsB += __shfl_xor_sync(0xffffffffu, lsB, 2);                           \
      DPSA(3); DPSB(3);                                                      \
      lsA += __shfl_xor_sync(0xffffffffu, lsA, 1);                           \
      lsB += __shfl_xor_sync(0xffffffffu, lsB, 1);                           \
      bfA = lsA; bfB = lsB; }

// quarter q at ring slot SL: refill (hoisted, depends only on consumed data),
// then wait, then 16 dp steps x 2 elements (B A B A groups).
#define QBLK2(SL, PAR, RSL, OK)                                              \
    { if (OK) { bulk_fill2(mbase + 8u * (RSL), sbase + (RSL) * 32768u,       \
                           gRA, gRB, lane); gRA += 4096; gRB += 4096; }      \
      mwait(mbase + 8u * (SL), (PAR)); __syncwarp();                         \
      GRPB2((SL) * SLOT_FLOATS);        GRPA2((SL) * SLOT_FLOATS + 1024);    \
      GRPB2((SL) * SLOT_FLOATS + 2048); GRPA2((SL) * SLOT_FLOATS + 3072); }

__global__ __launch_bounds__(32, 1)
void ctc_fwd_kernel(const int* __restrict__ y_true,
                    const float* __restrict__ y_pred,
                    float* __restrict__ out) {
    extern __shared__ float stg[];                 // 6 slots x 8192 floats
    __shared__ __align__(8) unsigned long long mb[NSLOT];
    const int pair = blockIdx.x, lane = threadIdx.x;
    const int bA = 2 * pair, bB = 2 * pair + 1;
    const float* gA = y_pred + (size_t)bA * Tn * Cn;
    const float* gB = y_pred + (size_t)bB * Tn * Cn;
    const uint32_t sbase = (uint32_t)__cvta_generic_to_shared(stg);
    const uint32_t mbase = (uint32_t)__cvta_generic_to_shared(mb);

    if (lane == 0) {
#pragma unroll
        for (int q = 0; q < NSLOT; q++)
            asm volatile("mbarrier.init.shared.b64 [%0], 1;" :: "r"(mbase + 8u * q) : "memory");
        asm volatile("fence.proxy.async.shared::cta;" ::: "memory");
    }
    __syncwarp();
#pragma unroll
    for (int q = 0; q < NSLOT; q++)                // prologue: quarters 0..5
        bulk_fill2(mbase + 8u * q, sbase + q * 32768u,
                   gA + q * 4096, gB + q * 4096, lane);

    const int l0a = y_true[bA * Un + 2 * lane];
    const int l1a = y_true[bA * Un + 2 * lane + 1];
    const int l0b = y_true[bB * Un + 2 * lane];
    const int l1b = y_true[bB * Un + 2 * lane + 1];
    const int lpa = __shfl_up_sync(0xffffffffu, l1a, 1);
    const int lpb = __shfl_up_sync(0xffffffffu, l1b, 1);
    const float sk1a = (lane == 0) ? 0.f : ((l0a != lpa) ? 1.f : 0.f);
    const float sk3a = (l1a != l0a) ? 1.f : 0.f;
    const float sk1b = (lane == 0) ? 0.f : ((l0b != lpb) ? 1.f : 0.f);
    const float sk3b = (l1b != l0b) ? 1.f : 0.f;

    const float* pBl = stg + BLANK;
    const float* p0a = stg + l0a;
    const float* p1a = stg + l1a;
    const float* p0b = stg + l0b;
    const float* p1b = stg + l1b;

    // ---- quarter 0 (slot 0, parity 0): init + t=1..3 peel + A B A (both)
    mwait(mbase, 0u);
    __syncwarp();
    float aA0=0.f,aA1=0.f,aA2=0.f,aA3=0.f,aA4=0.f;
    float aB0=0.f,aB1=0.f,aB2=0.f,aB3=0.f,aB4=0.f;
    if (lane == 0) {
        aA0 = pBl[0] + EPSF;    aA1 = p0a[0] + EPSF;
        aB0 = pBl[4096] + EPSF; aB1 = p0b[4096] + EPSF;
    }
#pragma unroll
    for (int t = 1; t < 4; t++) {
        float vBa = fmaf(pBl[t * Cn], Kc, EK);
        float v0a = fmaf(p0a[t * Cn], Kc, EK);
        float v1a = fmaf(p1a[t * Cn], Kc, EK);
        dp_step(aA0, aA1, aA2, aA3, aA4, vBa, v0a, v1a, sk1a, sk3a, lane);
        float vBb = fmaf(pBl[4096 + t * Cn], Kc, EK);
        float v0b = fmaf(p0b[4096 + t * Cn], Kc, EK);
        float v1b = fmaf(p1b[4096 + t * Cn], Kc, EK);
        dp_step(aB0, aB1, aB2, aB3, aB4, vBb, v0b, v1b, sk1b, sk3b, lane);
    }
    float lsA = 0.f, bfA = 1.f, lsB = 0.f, bfB = 1.f;
    int   Ea = 0, Eb = 0;
    const float* gRA = gA + NSLOT * 4096;          // next fill quarter: 6
    const float* gRB = gB + NSLOT * 4096;

    GRPA2(1024); GRPB2(2048); GRPA2(3072);

    // ---- quarters 1..30: i=0..4, positions k=1..6 (q = 6i+k)
    // slots 1,2,3,4,5,0; parity pe=i&1 for k=1..5, po for k=6; refill iff q<=26
#pragma unroll 1
    for (int i = 0; i < 5; i++) {
        const uint32_t pe = (uint32_t)(i & 1), po = pe ^ 1u;
        const int q6 = 6 * i;
        QBLK2(1, pe, 0, (q6 + 1) <= 26);
        QBLK2(2, pe, 1, (q6 + 2) <= 26);
        QBLK2(3, pe, 2, (q6 + 3) <= 26);
        QBLK2(4, pe, 3, (q6 + 4) <= 26);
        QBLK2(5, pe, 4, (q6 + 5) <= 26);
        QBLK2(0, po, 5, (q6 + 6) <= 26);
    }
    // ---- quarter 31 (slot 1, parity (31/6)&1 = 1), no refill
    QBLK2(1, 1u, 0, false);

    // stored tail = true_tail * 256^511 * 2^-E (E exactly bookkept)
    if (lane == 31) {
        const float LN2 = 0.69314718055994530942f;
        out[bA] = -(logf(aA3 + aA4) + (float)(Ea - 4088) * LN2);
        out[bB] = -(logf(aB3 + aB4) + (float)(Eb - 4088) * LN2);
    }
}

extern "C" void kernel_launch(void* const* d_in, const int* in_sizes, int n_in,
                              void* d_out, int out_size) {
    const int* y_true;
    const float* y_pred;
    if (in_sizes[0] == Bn * Un) {
        y_true = (const int*)d_in[0];
        y_pred = (const float*)d_in[1];
    } else {
        y_true = (const int*)d_in[1];
        y_pred = (const float*)d_in[0];
    }
    cudaFuncSetAttribute(ctc_fwd_kernel,
                         cudaFuncAttributeMaxDynamicSharedMemorySize, SMEM_TOTAL);
    ctc_fwd_kernel<<<Bn / 2, 32, SMEM_TOTAL>>>(y_true, y_pred, (float*)d_out);
}

// round 9
// speedup vs baseline: 1.0950x; 1.0950x over previous
#include <cuda_runtime.h>
#include <cstdint>
#include <cstddef>

// CTC batch cost (keras ctc_batch_cost), prob-domain forward, exact biased
// power-of-2 rescaling. NO smem/TMA: per-lane streaming LDG gather into a
// 16-row rotating register buffer (only the 3 needed classes per row are
// ever loaded). One warp per batch element. B=256,T=512,C=256(blank),U=64.
static constexpr int Bn = 256, Tn = 512, Cn = 256, Un = 64;
static constexpr int BLANK = Cn - 1;
static constexpr float EPSF = 1e-7f;
static constexpr float Kc = 256.f;      // exact power of 2
static constexpr float EK = 256.f * EPSF;
static constexpr int   BIAS = 48;       // pins working level ~2^48: no FTZ

// Lane L owns states 4L..4L+3; a4 = state 128 on lane 31 only (0 elsewhere).
__device__ __forceinline__ void dp_step(float& a0, float& a1, float& a2,
                                        float& a3, float& a4,
                                        float vB, float v0, float v1,
                                        float sk1, float sk3, int lane) {
    float pa3 = __shfl_up_sync(0xffffffffu, a3, 1);
    if (lane == 0) pa3 = 0.f;
    float na0 = (a0 + pa3) * vB;
    float na1 = fmaf(sk1, pa3, a0 + a1) * v0;
    float na2 = (a1 + a2) * vB;
    float na3 = fmaf(sk3, a1, a2 + a3) * v1;
    float na4 = (lane == 31) ? (a3 + a4) * vB : 0.f;
    a0 = na0; a1 = na1; a2 = na2; a3 = na3; a4 = na4;
}

// factors for buffer slots J..J+3 (values identical to the smem version)
#define EXTRACT(J)                                                           \
    float vB[4], v0[4], v1[4];                                               \
    _Pragma("unroll") for (int i_ = 0; i_ < 4; i_++) {                       \
        vB[i_] = fmaf(fB[(J) + i_], Kc, EK);                                 \
        v0[i_] = fmaf(f0[(J) + i_], Kc, EK);                                 \
        v1[i_] = fmaf(f1[(J) + i_], Kc, EK); }

// refill slots J..J+3 from the NEXT quarter (predicated off on last quarter)
#define RELOAD(J)                                                            \
    if (ld) { _Pragma("unroll") for (int i_ = 0; i_ < 4; i_++) {             \
        fB[(J) + i_] = __ldcs(nB + ((J) + i_) * Cn);                         \
        f0[(J) + i_] = __ldcs(n0 + ((J) + i_) * Cn);                         \
        f1[(J) + i_] = __ldcs(n1 + ((J) + i_) * Cn); } }

#define APPLY()                                                              \
    { uint32_t bb_ = __float_as_uint(bf);                                    \
      int sh_ = (int)(bb_ >> 23) - 127 - BIAS;                               \
      if (sh_ < -120) sh_ = -120;                                            \
      E += sh_;                                                              \
      float r_ = __uint_as_float((uint32_t)(127 - sh_) << 23);               \
      a0 *= r_; a1 *= r_; a2 *= r_; a3 *= r_; a4 *= r_; }

#define DPS(i_) dp_step(a0,a1,a2,a3,a4, vB[i_],v0[i_],v1[i_], sk1,sk3, lane)

// A-group: apply pending scale, 4 steps, snapshot sum, start butterfly
#define GRPA(J)                                                              \
    { EXTRACT(J); RELOAD(J); APPLY();                                        \
      DPS(0); DPS(1); DPS(2); DPS(3);                                        \
      ls = ((a0 + a1) + (a2 + a3)) + a4;                                     \
      ls += __shfl_xor_sync(0xffffffffu, ls, 16); }

// B-group: 4 steps with butterfly stages interleaved; bf ready at end
#define GRPB(J)                                                              \
    { EXTRACT(J); RELOAD(J);                                                 \
      DPS(0); ls += __shfl_xor_sync(0xffffffffu, ls, 8);                     \
      DPS(1); ls += __shfl_xor_sync(0xffffffffu, ls, 4);                     \
      DPS(2); ls += __shfl_xor_sync(0xffffffffu, ls, 2);                     \
      DPS(3); ls += __shfl_xor_sync(0xffffffffu, ls, 1);                     \
      bf = ls; }

__global__ __launch_bounds__(32)
void ctc_fwd_kernel(const int* __restrict__ y_true,
                    const float* __restrict__ y_pred,
                    float* __restrict__ out) {
    const int b = blockIdx.x, lane = threadIdx.x;
    const float* g = y_pred + (size_t)b * Tn * Cn;

    const int l0 = y_true[b * Un + 2 * lane];
    const int l1 = y_true[b * Un + 2 * lane + 1];
    const int lp = __shfl_up_sync(0xffffffffu, l1, 1);
    const float sk1 = (lane == 0) ? 0.f : ((l0 != lp) ? 1.f : 0.f);
    const float sk3 = (l1 != l0) ? 1.f : 0.f;

    // per-lane gather base pointers (vB is the same address across lanes)
    const float* rB = g + BLANK;
    const float* r0 = g + l0;
    const float* r1 = g + l1;

    // ---- prologue: load quarter 0 (rows 0..15) into the register buffer
    float fB[16], f0[16], f1[16];
#pragma unroll
    for (int j = 0; j < 16; j++) {
        fB[j] = __ldcs(rB + j * Cn);
        f0[j] = __ldcs(r0 + j * Cn);
        f1[j] = __ldcs(r1 + j * Cn);
    }
    // next-quarter load pointers (start at quarter 1 = row 16)
    const float* nB = rB + 16 * Cn;
    const float* n0 = r0 + 16 * Cn;
    const float* n1 = r1 + 16 * Cn;
    bool ld = true;

    // ---- quarter 0: t=0 init + t=1..3 peel (slots 0..3), reload 0..3,
    //      then A(4) B(8) A(12) exactly as the smem version
    float a0 = 0.f, a1 = 0.f, a2 = 0.f, a3 = 0.f, a4 = 0.f;
    if (lane == 0) { a0 = fB[0] + EPSF; a1 = f0[0] + EPSF; }
#pragma unroll
    for (int t = 1; t < 4; t++) {
        float vb = fmaf(fB[t], Kc, EK);
        float w0 = fmaf(f0[t], Kc, EK);
        float w1 = fmaf(f1[t], Kc, EK);
        dp_step(a0, a1, a2, a3, a4, vb, w0, w1, sk1, sk3, lane);
    }
    RELOAD(0);

    float ls = 0.f, bf = 1.f;
    int   E  = 0;

    GRPA(4); GRPB(8); GRPA(12);
    nB += 4096; n0 += 4096; n1 += 4096;              // now -> quarter 2

    // ---- quarters 1..31: consume quarter q, reload quarter q+1 (q<31)
#pragma unroll 1
    for (int q = 1; q < 32; q++) {
        ld = (q < 31);
        GRPB(0); GRPA(4); GRPB(8); GRPA(12);
        nB += 4096; n0 += 4096; n1 += 4096;
    }

    // stored tail = true_tail * 256^511 * 2^-E (E exactly bookkept)
    if (lane == 31) {
        const float LN2 = 0.69314718055994530942f;
        out[b] = -(logf(a3 + a4) + (float)(E - 4088) * LN2);
    }
}

extern "C" void kernel_launch(void* const* d_in, const int* in_sizes, int n_in,
                              void* d_out, int out_size) {
    const int* y_true;
    const float* y_pred;
    if (in_sizes[0] == Bn * Un) {
        y_true = (const int*)d_in[0];
        y_pred = (const float*)d_in[1];
    } else {
        y_true = (const int*)d_in[1];
        y_pred = (const float*)d_in[0];
    }
    ctc_fwd_kernel<<<Bn, 32>>>(y_true, y_pred, (float*)d_out);
}

// round 11
// speedup vs baseline: 1.4484x; 1.3228x over previous
#include <cuda_runtime.h>
#include <cstdint>
#include <cstddef>

// CTC batch cost (keras ctc_batch_cost), prob-domain forward, exact biased
// power-of-2 rescaling. HYBRID streaming: even 16-row quarters via TMA
// (cp.async.bulk -> 6x16KB smem ring), odd quarters via per-lane LDG gather
// into a 48-register buffer (32-row reload lead). Two independent HW supply
// paths per warp. One warp per batch element. B=256,T=512,C=256(blank),U=64.
static constexpr int Bn = 256, Tn = 512, Cn = 256, Un = 64;
static constexpr int BLANK = Cn - 1;
static constexpr float EPSF = 1e-7f;
static constexpr float Kc = 256.f;      // exact power of 2
static constexpr float EK = 256.f * EPSF;
static constexpr int   BIAS = 48;       // pins working level ~2^48: no FTZ
static constexpr int   NSLOT = 6;
static constexpr int   SMEM_TOTAL = NSLOT * 16384;   // 96KB

__device__ __forceinline__ void mwait(uint32_t mbar, uint32_t parity) {
    asm volatile(
        "{\n\t.reg .pred P;\n"
        "WL_%=:\n\t"
        "mbarrier.try_wait.parity.acquire.cta.shared::cta.b64 P, [%0], %1, 0x989680;\n\t"
        "@P bra WD_%=;\n\t"
        "bra WL_%=;\n"
        "WD_%=:\n\t}"
        :: "r"(mbar), "r"(parity) : "memory");
}

__device__ __forceinline__ void bulk_fill(uint32_t mbar, uint32_t sdst,
                                          const float* gsrc, int lane) {
    asm volatile(
        "{\n\t.reg .pred P;\n\t"
        "setp.eq.s32 P, %3, 0;\n\t"
        "@P mbarrier.arrive.expect_tx.shared.b64 _, [%0], 16384;\n\t"
        "@P cp.async.bulk.shared::cta.global.mbarrier::complete_tx::bytes [%1], [%2], 16384, [%0];\n\t"
        "}"
        :: "r"(mbar), "r"(sdst), "l"(gsrc), "r"(lane) : "memory");
}

// Lane L owns states 4L..4L+3; a4 = state 128 on lane 31 only (0 elsewhere).
__device__ __forceinline__ void dp_step(float& a0, float& a1, float& a2,
                                        float& a3, float& a4,
                                        float vB, float v0, float v1,
                                        float sk1, float sk3, int lane) {
    float pa3 = __shfl_up_sync(0xffffffffu, a3, 1);
    if (lane == 0) pa3 = 0.f;
    float na0 = (a0 + pa3) * vB;
    float na1 = fmaf(sk1, pa3, a0 + a1) * v0;
    float na2 = (a1 + a2) * vB;
    float na3 = fmaf(sk3, a1, a2 + a3) * v1;
    float na4 = (lane == 31) ? (a3 + a4) * vB : 0.f;
    a0 = na0; a1 = na1; a2 = na2; a3 = na3; a4 = na4;
}

#define APPLY()                                                              \
    { uint32_t bb_ = __float_as_uint(bf);                                    \
      int sh_ = (int)(bb_ >> 23) - 127 - BIAS;                               \
      if (sh_ < -120) sh_ = -120;                                            \
      E += sh_;                                                              \
      float r_ = __uint_as_float((uint32_t)(127 - sh_) << 23);               \
      a0 *= r_; a1 *= r_; a2 *= r_; a3 *= r_; a4 *= r_; }

#define DPS(i_) dp_step(a0,a1,a2,a3,a4, vB[i_],v0[i_],v1[i_], sk1,sk3, lane)

// ---- smem-sourced factors (TMA quarters) ----
#define LOADV_S(OFF)                                                         \
    float vB[4], v0[4], v1[4];                                               \
    _Pragma("unroll") for (int i_ = 0; i_ < 4; i_++) {                       \
        vB[i_] = fmaf(pBs[(OFF) + i_ * Cn], Kc, EK);                         \
        v0[i_] = fmaf(p0s[(OFF) + i_ * Cn], Kc, EK);                         \
        v1[i_] = fmaf(p1s[(OFF) + i_ * Cn], Kc, EK); }

#define GRPA_S(OFF)                                                          \
    { LOADV_S(OFF); APPLY();                                                 \
      DPS(0); DPS(1); DPS(2); DPS(3);                                        \
      ls = ((a0 + a1) + (a2 + a3)) + a4;                                     \
      ls += __shfl_xor_sync(0xffffffffu, ls, 16); }

#define GRPB_S(OFF)                                                          \
    { LOADV_S(OFF);                                                          \
      DPS(0); ls += __shfl_xor_sync(0xffffffffu, ls, 8);                     \
      DPS(1); ls += __shfl_xor_sync(0xffffffffu, ls, 4);                     \
      DPS(2); ls += __shfl_xor_sync(0xffffffffu, ls, 2);                     \
      DPS(3); ls += __shfl_xor_sync(0xffffffffu, ls, 1);                     \
      bf = ls; }

// ---- register-sourced factors (LDG quarters) ----
#define EXTRACT(J)                                                           \
    float vB[4], v0[4], v1[4];                                               \
    _Pragma("unroll") for (int i_ = 0; i_ < 4; i_++) {                       \
        vB[i_] = fmaf(fB[(J) + i_], Kc, EK);                                 \
        v0[i_] = fmaf(f0[(J) + i_], Kc, EK);                                 \
        v1[i_] = fmaf(f1[(J) + i_], Kc, EK); }

#define RELOAD(J)                                                            \
    if (ld) { _Pragma("unroll") for (int i_ = 0; i_ < 4; i_++) {             \
        fB[(J) + i_] = __ldcs(nB + ((J) + i_) * Cn);                         \
        f0[(J) + i_] = __ldcs(n0 + ((J) + i_) * Cn);                         \
        f1[(J) + i_] = __ldcs(n1 + ((J) + i_) * Cn); } }

#define GRPA_R(J)                                                            \
    { EXTRACT(J); RELOAD(J); APPLY();                                        \
      DPS(0); DPS(1); DPS(2); DPS(3);                                        \
      ls = ((a0 + a1) + (a2 + a3)) + a4;                                     \
      ls += __shfl_xor_sync(0xffffffffu, ls, 16); }

#define GRPB_R(J)                                                            \
    { EXTRACT(J); RELOAD(J);                                                 \
      DPS(0); ls += __shfl_xor_sync(0xffffffffu, ls, 8);                     \
      DPS(1); ls += __shfl_xor_sync(0xffffffffu, ls, 4);                     \
      DPS(2); ls += __shfl_xor_sync(0xffffffffu, ls, 2);                     \
      DPS(3); ls += __shfl_xor_sync(0xffffffffu, ls, 1);                     \
      bf = ls; }

__global__ __launch_bounds__(32)
void ctc_fwd_kernel(const int* __restrict__ y_true,
                    const float* __restrict__ y_pred,
                    float* __restrict__ out) {
    extern __shared__ float stg[];                 // 6 x 4096 floats
    __shared__ __align__(8) unsigned long long mb[NSLOT];
    const int b = blockIdx.x, lane = threadIdx.x;
    const float* g = y_pred + (size_t)b * Tn * Cn;
    const uint32_t sbase = (uint32_t)__cvta_generic_to_shared(stg);
    const uint32_t mbase = (uint32_t)__cvta_generic_to_shared(mb);

    if (lane == 0) {
#pragma unroll
        for (int q = 0; q < NSLOT; q++)
            asm volatile("mbarrier.init.shared.b64 [%0], 1;" :: "r"(mbase + 8u * q) : "memory");
        asm volatile("fence.proxy.async.shared::cta;" ::: "memory");
    }
    __syncwarp();
    // TMA prologue: slots 0..5 <- even quarters 0..5 (rows 32e..32e+15)
#pragma unroll
    for (int e = 0; e < NSLOT; e++)
        bulk_fill(mbase + 8u * e, sbase + e * 16384u, g + e * 8192, lane);

    const int l0 = y_true[b * Un + 2 * lane];
    const int l1 = y_true[b * Un + 2 * lane + 1];
    const int lp = __shfl_up_sync(0xffffffffu, l1, 1);
    const float sk1 = (lane == 0) ? 0.f : ((l0 != lp) ? 1.f : 0.f);
    const float sk3 = (l1 != l0) ? 1.f : 0.f;

    // LDG prologue: odd quarter 1 (rows 16..31) into the register buffer
    const float* rB = g + BLANK;
    const float* r0 = g + l0;
    const float* r1 = g + l1;
    float fB[16], f0[16], f1[16];
#pragma unroll
    for (int j = 0; j < 16; j++) {
        fB[j] = __ldcs(rB + (16 + j) * Cn);
        f0[j] = __ldcs(r0 + (16 + j) * Cn);
        f1[j] = __ldcs(r1 + (16 + j) * Cn);
    }
    // reload targets: next odd quarter (3 -> rows 48..63), advance 32 rows
    const float* nB = rB + 48 * Cn;
    const float* n0 = r0 + 48 * Cn;
    const float* n1 = r1 + 48 * Cn;
    const float* gE = g + NSLOT * 8192;            // next TMA fill: even q 6
    bool ld = true;

    // ---- even quarter 0 (slot 0, parity 0): init + peel t=1..3 + A B A
    mwait(mbase, 0u);
    __syncwarp();
    const float* pBs = stg + BLANK;
    const float* p0s = stg + l0;
    const float* p1s = stg + l1;
    float a0 = 0.f, a1 = 0.f, a2 = 0.f, a3 = 0.f, a4 = 0.f;
    if (lane == 0) { a0 = pBs[0] + EPSF; a1 = p0s[0] + EPSF; }
#pragma unroll
    for (int t = 1; t < 4; t++) {
        float vb = fmaf(pBs[t * Cn], Kc, EK);
        float w0 = fmaf(p0s[t * Cn], Kc, EK);
        float w1 = fmaf(p1s[t * Cn], Kc, EK);
        dp_step(a0, a1, a2, a3, a4, vb, w0, w1, sk1, sk3, lane);
    }
    float ls = 0.f, bf = 1.f;
    int   E  = 0;
    GRPA_S(4 * Cn); GRPB_S(8 * Cn); GRPA_S(12 * Cn);

    // ---- odd quarter 1 (registers), reload -> odd quarter 3
    GRPB_R(0); GRPA_R(4); GRPB_R(8); GRPA_R(12);
    nB += 8192; n0 += 8192; n1 += 8192;

    // ---- main: i = 1..15, even quarter i (TMA) then odd quarter 2i+1 (regs)
#pragma unroll 1
    for (int i = 1; i < 16; i++) {
        const int s  = i % NSLOT;
        const int rs = (i - 1) % NSLOT;
        const uint32_t par = (i >= 6 && i < 12) ? 1u : 0u;
        if (i <= 10) {                              // refill: even quarter i+5
            bulk_fill(mbase + 8u * rs, sbase + rs * 16384u, gE, lane);
            gE += 8192;
        }
        mwait(mbase + 8u * s, par);
        __syncwarp();
        const float* base = stg + s * 4096;
        pBs = base + BLANK; p0s = base + l0; p1s = base + l1;
        GRPB_S(0); GRPA_S(4 * Cn); GRPB_S(8 * Cn); GRPA_S(12 * Cn);

        ld = (i <= 14);                             // last reload target: q31
        GRPB_R(0); GRPA_R(4); GRPB_R(8); GRPA_R(12);
        nB += 8192; n0 += 8192; n1 += 8192;
    }

    // stored tail = true_tail * 256^511 * 2^-E (E exactly bookkept)
    if (lane == 31) {
        const float LN2 = 0.69314718055994530942f;
        out[b] = -(logf(a3 + a4) + (float)(E - 4088) * LN2);
    }
}

extern "C" void kernel_launch(void* const* d_in, const int* in_sizes, int n_in,
                              void* d_out, int out_size) {
    const int* y_true;
    const float* y_pred;
    if (in_sizes[0] == Bn * Un) {
        y_true = (const int*)d_in[0];
        y_pred = (const float*)d_in[1];
    } else {
        y_true = (const int*)d_in[1];
        y_pred = (const float*)d_in[0];
    }
    cudaFuncSetAttribute(ctc_fwd_kernel,
                         cudaFuncAttributeMaxDynamicSharedMemorySize, SMEM_TOTAL);
    ctc_fwd_kernel<<<Bn, 32, SMEM_TOTAL>>>(y_true, y_pred, (float*)d_out);
}

// round 15
// speedup vs baseline: 1.6801x; 1.1600x over previous
#include <cuda_runtime.h>
#include <cstdint>
#include <cstddef>

// CTC batch cost (keras ctc_batch_cost), prob-domain forward, exact biased
// power-of-2 rescaling, cp.async.bulk streaming. 96KB ring = 6 x 16KB
// quarters (16 rows x 1KB). Refills hoisted BEFORE the mbarrier wait (they
// depend only on already-consumed quarters). One warp per batch element.
// B=256, T=512, C=256 (blank=255), U=64, S=129.
static constexpr int Bn = 256, Tn = 512, Cn = 256, Un = 64;
static constexpr int BLANK = Cn - 1;
static constexpr float EPSF = 1e-7f;
static constexpr float Kc = 256.f;      // exact power of 2
static constexpr float EK = 256.f * EPSF;
static constexpr int   BIAS = 48;       // pins working level ~2^48: no FTZ
static constexpr int   NSLOT = 6;
static constexpr int   SMEM_TOTAL = NSLOT * 16384;   // 96KB

__device__ __forceinline__ void mwait(uint32_t mbar, uint32_t parity) {
    asm volatile(
        "{\n\t.reg .pred P;\n"
        "WL_%=:\n\t"
        "mbarrier.try_wait.parity.acquire.cta.shared::cta.b64 P, [%0], %1, 0x989680;\n\t"
        "@P bra WD_%=;\n\t"
        "bra WL_%=;\n"
        "WD_%=:\n\t}"
        :: "r"(mbar), "r"(parity) : "memory");
}

// lane 0 (predicated): expect_tx + 16KB bulk copy gmem->smem
__device__ __forceinline__ void bulk_fill(uint32_t mbar, uint32_t sdst,
                                          const float* gsrc, int lane) {
    asm volatile(
        "{\n\t.reg .pred P;\n\t"
        "setp.eq.s32 P, %3, 0;\n\t"
        "@P mbarrier.arrive.expect_tx.shared.b64 _, [%0], 16384;\n\t"
        "@P cp.async.bulk.shared::cta.global.mbarrier::complete_tx::bytes [%1], [%2], 16384, [%0];\n\t"
        "}"
        :: "r"(mbar), "r"(sdst), "l"(gsrc), "r"(lane) : "memory");
}

// Lane L owns states 4L..4L+3; a4 = state 128 on lane 31 only (0 elsewhere).
__device__ __forceinline__ void dp_step(float& a0, float& a1, float& a2,
                                        float& a3, float& a4,
                                        float vB, float v0, float v1,
                                        float sk1, float sk3, int lane) {
    float pa3 = __shfl_up_sync(0xffffffffu, a3, 1);
    if (lane == 0) pa3 = 0.f;
    float na0 = (a0 + pa3) * vB;
    float na1 = fmaf(sk1, pa3, a0 + a1) * v0;
    float na2 = (a1 + a2) * vB;
    float na3 = fmaf(sk3, a1, a2 + a3) * v1;
    float na4 = (lane == 31) ? (a3 + a4) * vB : 0.f;
    a0 = na0; a1 = na1; a2 = na2; a3 = na3; a4 = na4;
}

#define LOADV(SLOT)                                                          \
    { _Pragma("unroll") for (int i_ = 0; i_ < 4; i_++) {                     \
        vB[i_] = fmaf(pB[((SLOT) + i_) * Cn], Kc, EK);                       \
        v0[i_] = fmaf(p0[((SLOT) + i_) * Cn], Kc, EK);                       \
        v1[i_] = fmaf(p1[((SLOT) + i_) * Cn], Kc, EK); } }

#define APPLY()                                                              \
    { uint32_t bb_ = __float_as_uint(bf);                                    \
      int sh_ = (int)(bb_ >> 23) - 127 - BIAS;                               \
      if (sh_ < -120) sh_ = -120;                                            \
      E += sh_;                                                              \
      float r_ = __uint_as_float((uint32_t)(127 - sh_) << 23);               \
      a0 *= r_; a1 *= r_; a2 *= r_; a3 *= r_; a4 *= r_; }

#define DPS(i_) dp_step(a0,a1,a2,a3,a4, vB[i_],v0[i_],v1[i_], sk1,sk3, lane)

// A-group: apply pending scale, 4 steps, snapshot sum, start butterfly
#define GRPA(SLOT)                                                           \
    { float vB[4], v0[4], v1[4]; LOADV(SLOT); APPLY();                       \
      DPS(0); DPS(1); DPS(2); DPS(3);                                        \
      ls = ((a0 + a1) + (a2 + a3)) + a4;                                     \
      ls += __shfl_xor_sync(0xffffffffu, ls, 16); }

// B-group: 4 steps with butterfly stages interleaved; bf ready at end
#define GRPB(SLOT)                                                           \
    { float vB[4], v0[4], v1[4]; LOADV(SLOT);                                \
      DPS(0); ls += __shfl_xor_sync(0xffffffffu, ls, 8);                     \
      DPS(1); ls += __shfl_xor_sync(0xffffffffu, ls, 4);                     \
      DPS(2); ls += __shfl_xor_sync(0xffffffffu, ls, 2);                     \
      DPS(3); ls += __shfl_xor_sync(0xffffffffu, ls, 1);                     \
      bf = ls; }

// quarter q at ring slot SL: refill issued BEFORE the wait (its target slot
// was consumed last quarter; its source depends on nothing pending), then
// wait for this quarter's data, then 16 dp steps (B A B A).
#define QBLK(SL, PAR, RSL, OK)                                               \
    { if (OK) { bulk_fill(mbase + 8u * (RSL), sbase + (RSL) * 16384u, gR, lane); \
                gR += 4096; }                                                \
      mwait(mbase + 8u * (SL), (PAR)); __syncwarp();                         \
      GRPB(16 * (SL)); GRPA(16 * (SL) + 4);                                  \
      GRPB(16 * (SL) + 8); GRPA(16 * (SL) + 12); }

__global__ __launch_bounds__(32)
void ctc_fwd_kernel(const int* __restrict__ y_true,
                    const float* __restrict__ y_pred,
                    float* __restrict__ out) {
    extern __shared__ float stg[];                 // 96 rows x 256 f32
    __shared__ __align__(8) unsigned long long mb[NSLOT];
    const int b = blockIdx.x, lane = threadIdx.x;
    const float* g = y_pred + (size_t)b * Tn * Cn;
    const uint32_t sbase = (uint32_t)__cvta_generic_to_shared(stg);
    const uint32_t mbase = (uint32_t)__cvta_generic_to_shared(mb);

    if (lane == 0) {
#pragma unroll
        for (int q = 0; q < NSLOT; q++)
            asm volatile("mbarrier.init.shared.b64 [%0], 1;" :: "r"(mbase + 8u * q) : "memory");
        asm volatile("fence.proxy.async.shared::cta;" ::: "memory");
    }
    __syncwarp();
#pragma unroll
    for (int q = 0; q < NSLOT; q++)                // prologue: quarters 0..5
        bulk_fill(mbase + 8u * q, sbase + q * 16384u, g + q * 4096, lane);

    const int l0 = y_true[b * Un + 2 * lane];
    const int l1 = y_true[b * Un + 2 * lane + 1];
    const int lp = __shfl_up_sync(0xffffffffu, l1, 1);
    const float sk1 = (lane == 0) ? 0.f : ((l0 != lp) ? 1.f : 0.f);
    const float sk3 = (l1 != l0) ? 1.f : 0.f;

    const float* pB = stg + BLANK;
    const float* p0 = stg + l0;
    const float* p1 = stg + l1;

    // ---- quarter 0 (slot 0, parity 0): t=0 init + t=1..3 peel + A B A
    mwait(mbase, 0u);
    __syncwarp();
    float a0 = 0.f, a1 = 0.f, a2 = 0.f, a3 = 0.f, a4 = 0.f;
    if (lane == 0) { a0 = pB[0] + EPSF; a1 = p0[0] + EPSF; }
#pragma unroll
    for (int t = 1; t < 4; t++) {
        float vB = fmaf(pB[t * Cn], Kc, EK);
        float v0 = fmaf(p0[t * Cn], Kc, EK);
        float v1 = fmaf(p1[t * Cn], Kc, EK);
        dp_step(a0, a1, a2, a3, a4, vB, v0, v1, sk1, sk3, lane);
    }
    float ls = 0.f, bf = 1.f;
    int   E  = 0;
    const float* gR = g + NSLOT * 4096;            // next stream quarter: 6

    GRPA(4); GRPB(8); GRPA(12);

    // ---- quarters 1..30: i=0..4, positions k=1..6 (q = 6i+k)
    // slots 1,2,3,4,5,0; parity pe=i&1 for k=1..5, po for k=6; refill iff q<=26
#pragma unroll 1
    for (int i = 0; i < 5; i++) {
        const uint32_t pe = (uint32_t)(i & 1), po = pe ^ 1u;
        const int q6 = 6 * i;
        QBLK(1, pe, 0, (q6 + 1) <= 26);
        QBLK(2, pe, 1, (q6 + 2) <= 26);
        QBLK(3, pe, 2, (q6 + 3) <= 26);
        QBLK(4, pe, 3, (q6 + 4) <= 26);
        QBLK(5, pe, 4, (q6 + 5) <= 26);
        QBLK(0, po, 5, (q6 + 6) <= 26);
    }
    // ---- quarter 31 (slot 1, parity (31/6)&1 = 1), no refill
    QBLK(1, 1u, 0, false);

    // stored tail = true_tail * 256^511 * 2^-E (E exactly bookkept)
    if (lane == 31) {
        const float LN2 = 0.69314718055994530942f;
        out[b] = -(logf(a3 + a4) + (float)(E - 4088) * LN2);
    }
}

extern "C" void kernel_launch(void* const* d_in, const int* in_sizes, int n_in,
                              void* d_out, int out_size) {
    const int* y_true;
    const float* y_pred;
    if (in_sizes[0] == Bn * Un) {
        y_true = (const int*)d_in[0];
        y_pred = (const float*)d_in[1];
    } else {
        y_true = (const int*)d_in[1];
        y_pred = (const float*)d_in[0];
    }
    cudaFuncSetAttribute(ctc_fwd_kernel,
                         cudaFuncAttributeMaxDynamicSharedMemorySize, SMEM_TOTAL);
    ctc_fwd_kernel<<<Bn, 32, SMEM_TOTAL>>>(y_true, y_pred, (float*)d_out);
}